// round 16
// baseline (speedup 1.0000x reference)
#include <cuda_runtime.h>
#include <cuda_bf16.h>
#include <cuda_fp16.h>
#include <cstdint>

#define Bn  16
#define Tn  2048
#define Cn  384
#define DKn 64

// fp16 operands for attention (Q/P need hi only; K/V split hi+lo)
__device__ __align__(16) __half g_qh [Bn * Tn * DKn];
__device__ __align__(16) __half g_kh [Bn * Tn * DKn];
__device__ __align__(16) __half g_kl [Bn * Tn * DKn];
__device__ __align__(16) __half g_vth[Bn * DKn * Tn];   // [b][d][t]
__device__ __align__(16) __half g_vtl[Bn * DKn * Tn];
// Pre-transposed, pre-split fp16 weights for proj: [n][k], n 0..191 = [Q|K|V]
__device__ __align__(16) __half g_wth[192 * Cn];
__device__ __align__(16) __half g_wtl[192 * Cn];

// ===================== helpers =====================
__device__ __forceinline__ uint32_t smem_u32(const void* p) {
    uint32_t a;
    asm("{ .reg .u64 t; cvta.to.shared.u64 t, %1; cvt.u32.u64 %0, t; }" : "=r"(a) : "l"(p));
    return a;
}
// fp16 pack / split
__device__ __forceinline__ uint32_t packh2(float e0, float e1) {
    __half2 h = __floats2half2_rn(e0, e1);
    return *reinterpret_cast<uint32_t*>(&h);
}
__device__ __forceinline__ void split2h(float e0, float e1, uint32_t& hi, uint32_t& lo) {
    __half2 h = __floats2half2_rn(e0, e1);
    float2 hf = __half22float2(h);
    hi = *reinterpret_cast<uint32_t*>(&h);
    __half2 l = __floats2half2_rn(e0 - hf.x, e1 - hf.y);
    lo = *reinterpret_cast<uint32_t*>(&l);
}
__device__ __forceinline__ float ex2f(float x) {
    float r;
    asm("ex2.approx.f32 %0, %1;" : "=f"(r) : "f"(x));
    return r;
}
__device__ __forceinline__ void ldsm4(uint32_t r[4], uint32_t addr) {
    asm volatile("ldmatrix.sync.aligned.m8n8.x4.shared.b16 {%0,%1,%2,%3}, [%4];"
        : "=r"(r[0]), "=r"(r[1]), "=r"(r[2]), "=r"(r[3]) : "r"(addr));
}
__device__ __forceinline__ void mma16816h(float c[4], const uint32_t a[4],
                                          uint32_t b0, uint32_t b1) {
    asm volatile(
        "mma.sync.aligned.m16n8k16.row.col.f32.f16.f16.f32 "
        "{%0,%1,%2,%3},{%4,%5,%6,%7},{%8,%9},{%0,%1,%2,%3};"
        : "+f"(c[0]), "+f"(c[1]), "+f"(c[2]), "+f"(c[3])
        : "r"(a[0]), "r"(a[1]), "r"(a[2]), "r"(a[3]), "r"(b0), "r"(b1));
}
#define CP16(sm, gp) \
    asm volatile("cp.async.cg.shared.global [%0], [%1], 16;" :: "r"(sm), "l"(gp) : "memory")
#define CP_COMMIT() asm volatile("cp.async.commit_group;" ::: "memory")
#define CP_WAIT(n)  asm volatile("cp.async.wait_group %0;" :: "n"(n) : "memory")

extern __shared__ __align__(16) char dsmem[];

// ===================== prep_w: transpose + split W once (fp16, coalesced) ===
__global__ __launch_bounds__(256) void prep_w(
    const float* __restrict__ WQ,
    const float* __restrict__ WK,
    const float* __restrict__ WV)
{
    __shared__ float sw[64][65];
    const int tid = threadIdx.x;
    const int m   = blockIdx.x / 6;
    const int kk  = (blockIdx.x % 6) * 64;
    const float* W = (m == 0) ? WQ : ((m == 1) ? WK : WV);

#pragma unroll
    for (int it = 0; it < 4; it++) {
        int idx = tid + (it << 8);
        int k = idx >> 4, n4 = (idx & 15) << 2;
        float4 v = *(const float4*)(W + (size_t)(kk + k) * DKn + n4);
        sw[k][n4] = v.x; sw[k][n4 + 1] = v.y; sw[k][n4 + 2] = v.z; sw[k][n4 + 3] = v.w;
    }
    __syncthreads();

#pragma unroll
    for (int it = 0; it < 2; it++) {
        int idx = tid + (it << 8);
        int n = idx >> 3, k0 = (idx & 7) << 3;
        uint32_t h[4], lo[4];
#pragma unroll
        for (int j = 0; j < 4; j++)
            split2h(sw[k0 + 2 * j][n], sw[k0 + 2 * j + 1][n], h[j], lo[j]);
        size_t off = (size_t)(m * 64 + n) * Cn + kk + k0;
        *(uint4*)(g_wth + off) = make_uint4(h[0], h[1], h[2], h[3]);
        *(uint4*)(g_wtl + off) = make_uint4(lo[0], lo[1], lo[2], lo[3]);
    }
}

// ===================== projection: 64-row CTAs, 2/SM, x direct from global ==
// smem: W double buffer only (each 48KB: hi +0, lo +24576)
#define P_WT0 0u
#define P_WSTRIDE 49152u
#define PROJ_SMEM (98304u + 128u)

// Q pre-scale: 0.125 * log2(e)  (exp2-domain softmax downstream)
#define QSCALE 0.180336878f

__device__ __forceinline__ void stage_wt_async128(uint32_t dst, int kk, int tid) {
#pragma unroll
    for (int i = 0; i < 12; i++) {           // 1536 = 192 rows x 8 units
        int idx = tid + (i << 7);
        int n = idx >> 3, u = idx & 7;
        uint32_t sw = (uint32_t)n * 128u + (uint32_t)((u ^ (n & 7)) << 4);
        CP16(dst + sw,          g_wth + n * Cn + kk + (u << 3));
        CP16(dst + 24576u + sw, g_wtl + n * Cn + kk + (u << 3));
    }
}

__global__ __launch_bounds__(128, 2) void proj_tc_kernel(const float* __restrict__ x)
{
    uint32_t raw = smem_u32(dsmem);
    uint32_t sb  = (raw + 127u) & ~127u;
    char*    bp  = dsmem + (sb - raw);
    float (*vt)[65] = (float(*)[65])bp;      // epilogue overlay (buffer 0 region)

    const int tid = threadIdx.x;
    const int w   = tid >> 5;                // 0..3
    const int l   = tid & 31;
    const int r0  = blockIdx.x * 64;         // 64 rows per CTA

    float acc[24][4];
#pragma unroll
    for (int i = 0; i < 24; i++)
#pragma unroll
        for (int j = 0; j < 4; j++) acc[i][j] = 0.f;

    const int brow = l & 7;
    const int bu   = l >> 3;

    // x A-fragment base: row = r0 + w*16 + l/4 (+8), col pair base = (l&3)*2
    const float* xrow = x + (size_t)(r0 + (w << 4) + (l >> 2)) * Cn + ((l & 3) << 1);

    stage_wt_async128(sb + P_WT0, 0, tid);
    CP_COMMIT();

    for (int c = 0; c < Cn / 64; c++) {
        const int kk = c * 64;
        if (c + 1 < Cn / 64) {
            stage_wt_async128(sb + P_WT0 + (uint32_t)((c + 1) & 1) * P_WSTRIDE,
                              (c + 1) * 64, tid);
            CP_COMMIT();
            CP_WAIT(1);
        } else {
            CP_WAIT(0);
        }
        __syncthreads();

        const uint32_t wtb = sb + P_WT0 + (uint32_t)(c & 1) * P_WSTRIDE;

        // ---- A fragments: fp32 LDG -> fp16 pack (hi only) ----
        uint32_t ah[4][4];
#pragma unroll
        for (int ks = 0; ks < 4; ks++) {
            const float* p = xrow + kk + (ks << 4);
            float2 p0 = *(const float2*)(p);
            float2 p1 = *(const float2*)(p + 8 * Cn);      // row + 8
            float2 p2 = *(const float2*)(p + 8);           // col + 8
            float2 p3 = *(const float2*)(p + 8 * Cn + 8);
            ah[ks][0] = packh2(p0.x, p0.y);
            ah[ks][1] = packh2(p1.x, p1.y);
            ah[ks][2] = packh2(p2.x, p2.y);
            ah[ks][3] = packh2(p3.x, p3.y);
        }
#pragma unroll
        for (int nt = 0; nt < 24; nt++) {
            int rowb = (nt << 3) + brow;
            uint32_t rb = wtb + (uint32_t)rowb * 128u;
            uint32_t s0 = (uint32_t)((bu       ^ (rowb & 7)) << 4);
            uint32_t s1 = (uint32_t)(((4 + bu) ^ (rowb & 7)) << 4);
            uint32_t bh[8], bl[8];
            ldsm4(bh,     rb + s0);
            ldsm4(bh + 4, rb + s1);
            ldsm4(bl,     rb + 24576u + s0);
            ldsm4(bl + 4, rb + 24576u + s1);
#pragma unroll
            for (int s = 0; s < 4; s++) {
                mma16816h(acc[nt], ah[s], bh[2 * s], bh[2 * s + 1]);
                mma16816h(acc[nt], ah[s], bl[2 * s], bl[2 * s + 1]);
            }
        }
        __syncthreads();
    }

    // ---- epilogue: Q (xQSCALE) hi-only; K split fp16; V staged ----
    const int rl = (w << 4) + (l >> 2);
    const int cc = (l & 3) << 1;
    const size_t row0 = (size_t)(r0 + rl);
#pragma unroll
    for (int nt = 0; nt < 8; nt++) {
        int cidx = (nt << 3) + cc;
        uint32_t h, lo;
        *(uint32_t*)(g_qh + row0 * 64 + cidx) =
            packh2(acc[nt][0] * QSCALE, acc[nt][1] * QSCALE);
        *(uint32_t*)(g_qh + (row0 + 8) * 64 + cidx) =
            packh2(acc[nt][2] * QSCALE, acc[nt][3] * QSCALE);

        split2h(acc[nt + 8][0], acc[nt + 8][1], h, lo);
        *(uint32_t*)(g_kh + row0 * 64 + cidx) = h;
        *(uint32_t*)(g_kl + row0 * 64 + cidx) = lo;
        split2h(acc[nt + 8][2], acc[nt + 8][3], h, lo);
        *(uint32_t*)(g_kh + (row0 + 8) * 64 + cidx) = h;
        *(uint32_t*)(g_kl + (row0 + 8) * 64 + cidx) = lo;

        vt[rl][cidx]         = acc[nt + 16][0];
        vt[rl][cidx + 1]     = acc[nt + 16][1];
        vt[rl + 8][cidx]     = acc[nt + 16][2];
        vt[rl + 8][cidx + 1] = acc[nt + 16][3];
    }
    __syncthreads();

    // ---- V transposed write: g_vt[b][d][t], split fp16 ----
    {
        const int b  = r0 >> 11;
        const int t0 = r0 & 2047;
        const int d  = tid >> 1;             // 0..63
        const int tq = (tid & 1) << 5;       // 0 or 32
#pragma unroll
        for (int g = 0; g < 8; g++) {
            int tl = tq + g * 4;
            float v0 = vt[tl][d], v1 = vt[tl + 1][d];
            float v2 = vt[tl + 2][d], v3 = vt[tl + 3][d];
            uint32_t h0, h1, l0, l1;
            split2h(v0, v1, h0, l0);
            split2h(v2, v3, h1, l1);
            size_t off = ((size_t)(b * DKn + d) << 11) + t0 + tl;
            *(uint2*)(g_vth + off) = make_uint2(h0, h1);
            *(uint2*)(g_vtl + off) = make_uint2(l0, l1);
        }
    }
}

// ===================== attention: fp16 2-product, triple buffer =============
// smem: 3 KV buffers @0, each 32KB: KHI +0, KLO +8192, VHI +16384, VLO +24576
#define A_KHI 0u
#define A_KLO 8192u
#define A_VHI 16384u
#define A_VLO 24576u
#define ATTN_SMEM (98304u + 128u)

__device__ __forceinline__ void stage_kv_async(uint32_t dst, int b, int ks, int tid) {
    const __half* kh = g_kh + (((size_t)(b * Tn + ks)) << 6);
    const __half* kl = g_kl + (((size_t)(b * Tn + ks)) << 6);
    const __half* vh = g_vth + (((size_t)(b * DKn)) << 11) + ks;
    const __half* vl = g_vtl + (((size_t)(b * DKn)) << 11) + ks;
#pragma unroll
    for (int i = 0; i < 4; i++) {
        int idx = tid + (i << 7);
        int r = idx >> 3, u = idx & 7;
        uint32_t sw = (uint32_t)r * 128u + (uint32_t)((u ^ (r & 7)) << 4);
        CP16(dst + A_KHI + sw, kh + (r << 6) + (u << 3));
        CP16(dst + A_KLO + sw, kl + (r << 6) + (u << 3));
        CP16(dst + A_VHI + sw, vh + ((size_t)r << 11) + (u << 3));
        CP16(dst + A_VLO + sw, vl + ((size_t)r << 11) + (u << 3));
    }
}

__global__ __launch_bounds__(128, 2) void attn_kernel(float* __restrict__ out)
{
    uint32_t raw = smem_u32(dsmem);
    uint32_t sb  = (raw + 127u) & ~127u;

    const int tid = threadIdx.x;
    const int w   = tid >> 5;
    const int l   = tid & 31;

    const int bx = blockIdx.x;
    const int qt = 31 - (bx >> 4);          // heavy q-tiles first
    const int b  = bx & 15;
    const int q0 = qt << 6;
    const int ntiles = qt + 1;

    // prefetch first two K/V tiles
    stage_kv_async(sb, b, 0, tid);
    CP_COMMIT();
    if (ntiles > 1) {
        stage_kv_async(sb + 32768u, b, 64, tid);
        CP_COMMIT();
    }

    // ---- Q hi fragments directly from global ----
    uint32_t qh[4][4];
    {
        const int rowa = q0 + (w << 4) + (l >> 2);
        const int cb   = (l & 3) << 1;
        const __half* ph = g_qh + (((size_t)(b * Tn + rowa)) << 6) + cb;
#pragma unroll
        for (int ks = 0; ks < 4; ks++) {
            int c0 = ks << 4;
            qh[ks][0] = *(const uint32_t*)(ph + c0);
            qh[ks][1] = *(const uint32_t*)(ph + 512 + c0);
            qh[ks][2] = *(const uint32_t*)(ph + c0 + 8);
            qh[ks][3] = *(const uint32_t*)(ph + 512 + c0 + 8);
        }
    }

    float m0 = -3.0e38f, m1 = -3.0e38f, ls0 = 0.f, ls1 = 0.f;
    float o[8][4];
#pragma unroll
    for (int i = 0; i < 8; i++)
#pragma unroll
        for (int j = 0; j < 4; j++) o[i][j] = 0.f;

    const int wrow0 = q0 + (w << 4);
    const int brow  = l & 7;
    const int bu    = l >> 3;

    int cslot = 0, pslot = 2;               // it%3 and (it+2)%3
    for (int it = 0; it < ntiles; it++) {
        const int ks = it << 6;
        if (it + 1 < ntiles) { CP_WAIT(1); } else { CP_WAIT(0); }
        __syncthreads();
        if (it + 2 < ntiles) {
            stage_kv_async(sb + (uint32_t)pslot * 32768u, b, ks + 128, tid);
            CP_COMMIT();
        }
        const uint32_t kvb = sb + (uint32_t)cslot * 32768u;
        cslot = (cslot == 2) ? 0 : cslot + 1;
        pslot = (pslot == 2) ? 0 : pslot + 1;

        // ---- S = Q K^T : qh*kh + qh*kl ----
        float sc[8][4];
#pragma unroll
        for (int nt = 0; nt < 8; nt++) {
            int row = (nt << 3) + brow;
            uint32_t rb = kvb + (uint32_t)row * 128u;
            uint32_t s0 = (uint32_t)((bu       ^ (row & 7)) << 4);
            uint32_t s1 = (uint32_t)(((4 + bu) ^ (row & 7)) << 4);
            uint32_t kh8[8], kl8[8];
            ldsm4(kh8,     rb + A_KHI + s0);
            ldsm4(kh8 + 4, rb + A_KHI + s1);
            ldsm4(kl8,     rb + A_KLO + s0);
            ldsm4(kl8 + 4, rb + A_KLO + s1);
#pragma unroll
            for (int j = 0; j < 4; j++) sc[nt][j] = 0.f;
#pragma unroll
            for (int s = 0; s < 4; s++) {
                mma16816h(sc[nt], qh[s], kh8[2 * s], kh8[2 * s + 1]);
                mma16816h(sc[nt], qh[s], kl8[2 * s], kl8[2 * s + 1]);
            }
        }

        // ---- causal mask (diagonal tile only) ----
        const int R0 = wrow0 + (l >> 2);
        if (ks + 64 > wrow0) {
            int colb = ks + ((l & 3) << 1);
#pragma unroll
            for (int nt = 0; nt < 8; nt++) {
                int c0 = colb + (nt << 3);
                if (c0     > R0)     sc[nt][0] = -3.0e38f;
                if (c0 + 1 > R0)     sc[nt][1] = -3.0e38f;
                if (c0     > R0 + 8) sc[nt][2] = -3.0e38f;
                if (c0 + 1 > R0 + 8) sc[nt][3] = -3.0e38f;
            }
        }

        // ---- online softmax (exp2 domain) ----
        float tm0 = -3.0e38f, tm1 = -3.0e38f;
#pragma unroll
        for (int nt = 0; nt < 8; nt++) {
            tm0 = fmaxf(tm0, fmaxf(sc[nt][0], sc[nt][1]));
            tm1 = fmaxf(tm1, fmaxf(sc[nt][2], sc[nt][3]));
        }
        tm0 = fmaxf(tm0, __shfl_xor_sync(0xffffffffu, tm0, 1));
        tm0 = fmaxf(tm0, __shfl_xor_sync(0xffffffffu, tm0, 2));
        tm1 = fmaxf(tm1, __shfl_xor_sync(0xffffffffu, tm1, 1));
        tm1 = fmaxf(tm1, __shfl_xor_sync(0xffffffffu, tm1, 2));
        float mn0 = fmaxf(m0, tm0), mn1 = fmaxf(m1, tm1);
        float c0 = ex2f(m0 - mn0), c1 = ex2f(m1 - mn1);

        float ps0 = 0.f, ps1 = 0.f;
        uint32_t phi[4][4];
#pragma unroll
        for (int s = 0; s < 4; s++) {
#pragma unroll
            for (int h = 0; h < 2; h++) {
                int nt = 2 * s + h;
                float p0 = ex2f(sc[nt][0] - mn0);
                float p1 = ex2f(sc[nt][1] - mn0);
                float p2 = ex2f(sc[nt][2] - mn1);
                float p3 = ex2f(sc[nt][3] - mn1);
                ps0 += p0 + p1;
                ps1 += p2 + p3;
                phi[s][2 * h]     = packh2(p0, p1);
                phi[s][2 * h + 1] = packh2(p2, p3);
            }
        }
        ps0 += __shfl_xor_sync(0xffffffffu, ps0, 1);
        ps0 += __shfl_xor_sync(0xffffffffu, ps0, 2);
        ps1 += __shfl_xor_sync(0xffffffffu, ps1, 1);
        ps1 += __shfl_xor_sync(0xffffffffu, ps1, 2);
        ls0 = ls0 * c0 + ps0;
        ls1 = ls1 * c1 + ps1;
        m0 = mn0; m1 = mn1;

        // ---- O = O*c + P V : ph*vh + ph*vl ----
#pragma unroll
        for (int nt = 0; nt < 8; nt++) {
            o[nt][0] *= c0; o[nt][1] *= c0;
            o[nt][2] *= c1; o[nt][3] *= c1;
        }
#pragma unroll
        for (int nt = 0; nt < 8; nt++) {
            int row = (nt << 3) + brow;
            uint32_t rb = kvb + (uint32_t)row * 128u;
            uint32_t s0 = (uint32_t)((bu       ^ (row & 7)) << 4);
            uint32_t s1 = (uint32_t)(((4 + bu) ^ (row & 7)) << 4);
            uint32_t vh8[8], vl8[8];
            ldsm4(vh8,     rb + A_VHI + s0);
            ldsm4(vh8 + 4, rb + A_VHI + s1);
            ldsm4(vl8,     rb + A_VLO + s0);
            ldsm4(vl8 + 4, rb + A_VLO + s1);
#pragma unroll
            for (int s = 0; s < 4; s++) {
                mma16816h(o[nt], phi[s], vh8[2 * s], vh8[2 * s + 1]);
                mma16816h(o[nt], phi[s], vl8[2 * s], vl8[2 * s + 1]);
            }
        }
    }

    const float inv0 = 1.f / ls0, inv1 = 1.f / ls1;
    const int R0g = q0 + (w << 4) + (l >> 2);
    float* o0p = out + (((size_t)(b * Tn + R0g)) << 6) + ((l & 3) << 1);
    float* o1p = o0p + (8 << 6);
#pragma unroll
    for (int nt = 0; nt < 8; nt++) {
        *(float2*)(o0p + (nt << 3)) = make_float2(o[nt][0] * inv0, o[nt][1] * inv0);
        *(float2*)(o1p + (nt << 3)) = make_float2(o[nt][2] * inv1, o[nt][3] * inv1);
    }
}

// ===================== launch =====================
extern "C" void kernel_launch(void* const* d_in, const int* in_sizes, int n_in,
                              void* d_out, int out_size)
{
    const float* x  = (const float*)d_in[0];
    const float* WQ = (const float*)d_in[1];
    const float* WK = (const float*)d_in[2];
    const float* WV = (const float*)d_in[3];
    float* out = (float*)d_out;

    cudaFuncSetAttribute(proj_tc_kernel,
                         cudaFuncAttributeMaxDynamicSharedMemorySize, PROJ_SMEM);
    cudaFuncSetAttribute(attn_kernel,
                         cudaFuncAttributeMaxDynamicSharedMemorySize, ATTN_SMEM);

    prep_w<<<18, 256>>>(WQ, WK, WV);
    proj_tc_kernel<<<512, 128, PROJ_SMEM>>>(x);
    attn_kernel<<<512, 128, ATTN_SMEM>>>(out);
}

// round 17
// speedup vs baseline: 1.1090x; 1.1090x over previous
#include <cuda_runtime.h>
#include <cuda_bf16.h>
#include <cuda_fp16.h>
#include <cstdint>

#define Bn  16
#define Tn  2048
#define Cn  384
#define DKn 64

// fp16 operands for attention (Q/P hi only; K split hi+lo; V hi only)
__device__ __align__(16) __half g_qh [Bn * Tn * DKn];
__device__ __align__(16) __half g_kh [Bn * Tn * DKn];
__device__ __align__(16) __half g_kl [Bn * Tn * DKn];
__device__ __align__(16) __half g_vth[Bn * DKn * Tn];   // [b][d][t]
// Pre-transposed, pre-split fp16 weights for proj: [n][k], n 0..191 = [Q|K|V]
__device__ __align__(16) __half g_wth[192 * Cn];
__device__ __align__(16) __half g_wtl[192 * Cn];

// ===================== helpers =====================
__device__ __forceinline__ uint32_t smem_u32(const void* p) {
    uint32_t a;
    asm("{ .reg .u64 t; cvta.to.shared.u64 t, %1; cvt.u32.u64 %0, t; }" : "=r"(a) : "l"(p));
    return a;
}
// fp16 pack / split
__device__ __forceinline__ uint32_t packh2(float e0, float e1) {
    __half2 h = __floats2half2_rn(e0, e1);
    return *reinterpret_cast<uint32_t*>(&h);
}
__device__ __forceinline__ void split2h(float e0, float e1, uint32_t& hi, uint32_t& lo) {
    __half2 h = __floats2half2_rn(e0, e1);
    float2 hf = __half22float2(h);
    hi = *reinterpret_cast<uint32_t*>(&h);
    __half2 l = __floats2half2_rn(e0 - hf.x, e1 - hf.y);
    lo = *reinterpret_cast<uint32_t*>(&l);
}
__device__ __forceinline__ float ex2f(float x) {
    float r;
    asm("ex2.approx.f32 %0, %1;" : "=f"(r) : "f"(x));
    return r;
}
__device__ __forceinline__ void ldsm4(uint32_t r[4], uint32_t addr) {
    asm volatile("ldmatrix.sync.aligned.m8n8.x4.shared.b16 {%0,%1,%2,%3}, [%4];"
        : "=r"(r[0]), "=r"(r[1]), "=r"(r[2]), "=r"(r[3]) : "r"(addr));
}
__device__ __forceinline__ void mma16816h(float c[4], const uint32_t a[4],
                                          uint32_t b0, uint32_t b1) {
    asm volatile(
        "mma.sync.aligned.m16n8k16.row.col.f32.f16.f16.f32 "
        "{%0,%1,%2,%3},{%4,%5,%6,%7},{%8,%9},{%0,%1,%2,%3};"
        : "+f"(c[0]), "+f"(c[1]), "+f"(c[2]), "+f"(c[3])
        : "r"(a[0]), "r"(a[1]), "r"(a[2]), "r"(a[3]), "r"(b0), "r"(b1));
}
#define CP16(sm, gp) \
    asm volatile("cp.async.cg.shared.global [%0], [%1], 16;" :: "r"(sm), "l"(gp) : "memory")
#define CP_COMMIT() asm volatile("cp.async.commit_group;" ::: "memory")
#define CP_WAIT(n)  asm volatile("cp.async.wait_group %0;" :: "n"(n) : "memory")

extern __shared__ __align__(16) char dsmem[];

// ===================== prep_w: transpose + split W once (fp16, coalesced) ===
__global__ __launch_bounds__(256) void prep_w(
    const float* __restrict__ WQ,
    const float* __restrict__ WK,
    const float* __restrict__ WV)
{
    __shared__ float sw[64][65];
    const int tid = threadIdx.x;
    const int m   = blockIdx.x / 6;
    const int kk  = (blockIdx.x % 6) * 64;
    const float* W = (m == 0) ? WQ : ((m == 1) ? WK : WV);

#pragma unroll
    for (int it = 0; it < 4; it++) {
        int idx = tid + (it << 8);
        int k = idx >> 4, n4 = (idx & 15) << 2;
        float4 v = *(const float4*)(W + (size_t)(kk + k) * DKn + n4);
        sw[k][n4] = v.x; sw[k][n4 + 1] = v.y; sw[k][n4 + 2] = v.z; sw[k][n4 + 3] = v.w;
    }
    __syncthreads();

#pragma unroll
    for (int it = 0; it < 2; it++) {
        int idx = tid + (it << 8);
        int n = idx >> 3, k0 = (idx & 7) << 3;
        uint32_t h[4], lo[4];
#pragma unroll
        for (int j = 0; j < 4; j++)
            split2h(sw[k0 + 2 * j][n], sw[k0 + 2 * j + 1][n], h[j], lo[j]);
        size_t off = (size_t)(m * 64 + n) * Cn + kk + k0;
        *(uint4*)(g_wth + off) = make_uint4(h[0], h[1], h[2], h[3]);
        *(uint4*)(g_wtl + off) = make_uint4(lo[0], lo[1], lo[2], lo[3]);
    }
}

// ===================== projection: fp16 2-term, async staging (r14 form) ====
#define P_X0 0u
#define P_XSTRIDE 36864u
#define P_WT0 73728u
#define P_WSTRIDE 49152u
#define PROJ_SMEM (172032u + 128u)

// Q pre-scale: 0.125 * log2(e)  (exp2-domain softmax downstream)
#define QSCALE 0.180336878f

__device__ __forceinline__ void stage_wt_async(uint32_t dst, int kk, int tid) {
#pragma unroll
    for (int i = 0; i < 6; i++) {
        int idx = tid + (i << 8);
        int n = idx >> 3, u = idx & 7;
        uint32_t sw = (uint32_t)n * 128u + (uint32_t)((u ^ (n & 7)) << 4);
        CP16(dst + sw,          g_wth + n * Cn + kk + (u << 3));
        CP16(dst + 24576u + sw, g_wtl + n * Cn + kk + (u << 3));
    }
}
__device__ __forceinline__ void stage_x_async(uint32_t dst, const float* xp, int tid) {
#pragma unroll
    for (int i = 0; i < 8; i++) {
        int idx = tid + (i << 8);
        int r = idx >> 4, u = idx & 15;
        CP16(dst + (uint32_t)r * 288u + (uint32_t)(u << 4),
             xp + (size_t)r * Cn + (u << 2));
    }
}

__global__ __launch_bounds__(256, 1) void proj_tc_kernel(const float* __restrict__ x)
{
    uint32_t raw = smem_u32(dsmem);
    uint32_t sb  = (raw + 127u) & ~127u;
    char*    bp  = dsmem + (sb - raw);
    float (*vt)[65] = (float(*)[65])(bp + P_WT0);

    const int tid = threadIdx.x;
    const int w   = tid >> 5;
    const int l   = tid & 31;
    const int r0  = blockIdx.x * 128;

    float acc[24][4];
#pragma unroll
    for (int i = 0; i < 24; i++)
#pragma unroll
        for (int j = 0; j < 4; j++) acc[i][j] = 0.f;

    const int brow = l & 7;
    const int bu   = l >> 3;
    const int ra   = (w << 4) + (l >> 2);

    stage_x_async(sb + P_X0, x + (size_t)r0 * Cn, tid);
    stage_wt_async(sb + P_WT0, 0, tid);
    CP_COMMIT();

    for (int c = 0; c < Cn / 64; c++) {
        if (c + 1 < Cn / 64) {
            stage_x_async(sb + P_X0 + (uint32_t)((c + 1) & 1) * P_XSTRIDE,
                          x + (size_t)r0 * Cn + (c + 1) * 64, tid);
            stage_wt_async(sb + P_WT0 + (uint32_t)((c + 1) & 1) * P_WSTRIDE,
                           (c + 1) * 64, tid);
            CP_COMMIT();
            CP_WAIT(1);
        } else {
            CP_WAIT(0);
        }
        __syncthreads();

        const char*    xb  = bp + P_X0 + (uint32_t)(c & 1) * P_XSTRIDE;
        const uint32_t wtb = sb + P_WT0 + (uint32_t)(c & 1) * P_WSTRIDE;

        // ---- A fragments: fp32 LDS -> fp16 pack (hi only) ----
        uint32_t ah[4][4];
        {
            const char* rowa = xb + (uint32_t)ra * 288u;
            const char* rowb = rowa + 8u * 288u;
#pragma unroll
            for (int ks = 0; ks < 4; ks++) {
                int c0 = (ks << 6) + ((l & 3) << 3);
                float2 p0 = *(const float2*)(rowa + c0);
                float2 p1 = *(const float2*)(rowb + c0);
                float2 p2 = *(const float2*)(rowa + c0 + 32);
                float2 p3 = *(const float2*)(rowb + c0 + 32);
                ah[ks][0] = packh2(p0.x, p0.y);
                ah[ks][1] = packh2(p1.x, p1.y);
                ah[ks][2] = packh2(p2.x, p2.y);
                ah[ks][3] = packh2(p3.x, p3.y);
            }
        }
#pragma unroll
        for (int nt = 0; nt < 24; nt++) {
            int rowb = (nt << 3) + brow;
            uint32_t rb = wtb + (uint32_t)rowb * 128u;
            uint32_t s0 = (uint32_t)((bu       ^ (rowb & 7)) << 4);
            uint32_t s1 = (uint32_t)(((4 + bu) ^ (rowb & 7)) << 4);
            uint32_t bh[8], bl[8];
            ldsm4(bh,     rb + s0);
            ldsm4(bh + 4, rb + s1);
            ldsm4(bl,     rb + 24576u + s0);
            ldsm4(bl + 4, rb + 24576u + s1);
#pragma unroll
            for (int s = 0; s < 4; s++) {
                mma16816h(acc[nt], ah[s], bh[2 * s], bh[2 * s + 1]);
                mma16816h(acc[nt], ah[s], bl[2 * s], bl[2 * s + 1]);
            }
        }
        __syncthreads();
    }

    // ---- epilogue: Q (xQSCALE) hi-only; K split fp16; V staged ----
    const int rl = (w << 4) + (l >> 2);
    const int cc = (l & 3) << 1;
    const size_t row0 = (size_t)(r0 + rl);
#pragma unroll
    for (int nt = 0; nt < 8; nt++) {
        int cidx = (nt << 3) + cc;
        uint32_t h, lo;
        *(uint32_t*)(g_qh + row0 * 64 + cidx) =
            packh2(acc[nt][0] * QSCALE, acc[nt][1] * QSCALE);
        *(uint32_t*)(g_qh + (row0 + 8) * 64 + cidx) =
            packh2(acc[nt][2] * QSCALE, acc[nt][3] * QSCALE);

        split2h(acc[nt + 8][0], acc[nt + 8][1], h, lo);
        *(uint32_t*)(g_kh + row0 * 64 + cidx) = h;
        *(uint32_t*)(g_kl + row0 * 64 + cidx) = lo;
        split2h(acc[nt + 8][2], acc[nt + 8][3], h, lo);
        *(uint32_t*)(g_kh + (row0 + 8) * 64 + cidx) = h;
        *(uint32_t*)(g_kl + (row0 + 8) * 64 + cidx) = lo;

        vt[rl][cidx]         = acc[nt + 16][0];
        vt[rl][cidx + 1]     = acc[nt + 16][1];
        vt[rl + 8][cidx]     = acc[nt + 16][2];
        vt[rl + 8][cidx + 1] = acc[nt + 16][3];
    }
    __syncthreads();

    // ---- V transposed write: g_vt[b][d][t], fp16 hi only ----
    {
        const int b  = r0 >> 11;
        const int t0 = r0 & 2047;
        const int d  = tid >> 2;
        const int tq = (tid & 3) << 5;
#pragma unroll
        for (int g = 0; g < 8; g++) {
            int tl = tq + g * 4;
            float v0 = vt[tl][d], v1 = vt[tl + 1][d];
            float v2 = vt[tl + 2][d], v3 = vt[tl + 3][d];
            uint32_t h0 = packh2(v0, v1);
            uint32_t h1 = packh2(v2, v3);
            size_t off = ((size_t)(b * DKn + d) << 11) + t0 + tl;
            *(uint2*)(g_vth + off) = make_uint2(h0, h1);
        }
    }
}

// ===================== attention: fp16, V 1-term, triple buffer =============
// smem: 3 KV buffers @0, each 24KB: KHI +0, KLO +8192, VHI +16384
#define A_KHI 0u
#define A_KLO 8192u
#define A_VHI 16384u
#define A_BSTRIDE 24576u
#define ATTN_SMEM (73728u + 128u)

__device__ __forceinline__ void stage_kv_async(uint32_t dst, int b, int ks, int tid) {
    const __half* kh = g_kh + (((size_t)(b * Tn + ks)) << 6);
    const __half* kl = g_kl + (((size_t)(b * Tn + ks)) << 6);
    const __half* vh = g_vth + (((size_t)(b * DKn)) << 11) + ks;
#pragma unroll
    for (int i = 0; i < 4; i++) {
        int idx = tid + (i << 7);
        int r = idx >> 3, u = idx & 7;
        uint32_t sw = (uint32_t)r * 128u + (uint32_t)((u ^ (r & 7)) << 4);
        CP16(dst + A_KHI + sw, kh + (r << 6) + (u << 3));
        CP16(dst + A_KLO + sw, kl + (r << 6) + (u << 3));
        CP16(dst + A_VHI + sw, vh + ((size_t)r << 11) + (u << 3));
    }
}

__global__ __launch_bounds__(128, 2) void attn_kernel(float* __restrict__ out)
{
    uint32_t raw = smem_u32(dsmem);
    uint32_t sb  = (raw + 127u) & ~127u;

    const int tid = threadIdx.x;
    const int w   = tid >> 5;
    const int l   = tid & 31;

    const int bx = blockIdx.x;
    const int qt = 31 - (bx >> 4);          // heavy q-tiles first
    const int b  = bx & 15;
    const int q0 = qt << 6;
    const int ntiles = qt + 1;

    // prefetch first two K/V tiles
    stage_kv_async(sb, b, 0, tid);
    CP_COMMIT();
    if (ntiles > 1) {
        stage_kv_async(sb + A_BSTRIDE, b, 64, tid);
        CP_COMMIT();
    }

    // ---- Q hi fragments directly from global ----
    uint32_t qh[4][4];
    {
        const int rowa = q0 + (w << 4) + (l >> 2);
        const int cb   = (l & 3) << 1;
        const __half* ph = g_qh + (((size_t)(b * Tn + rowa)) << 6) + cb;
#pragma unroll
        for (int ks = 0; ks < 4; ks++) {
            int c0 = ks << 4;
            qh[ks][0] = *(const uint32_t*)(ph + c0);
            qh[ks][1] = *(const uint32_t*)(ph + 512 + c0);
            qh[ks][2] = *(const uint32_t*)(ph + c0 + 8);
            qh[ks][3] = *(const uint32_t*)(ph + 512 + c0 + 8);
        }
    }

    float m0 = -3.0e38f, m1 = -3.0e38f, ls0 = 0.f, ls1 = 0.f;
    float o[8][4];
#pragma unroll
    for (int i = 0; i < 8; i++)
#pragma unroll
        for (int j = 0; j < 4; j++) o[i][j] = 0.f;

    const int wrow0 = q0 + (w << 4);
    const int brow  = l & 7;
    const int bu    = l >> 3;

    int cslot = 0, pslot = 2;               // it%3 and (it+2)%3
    for (int it = 0; it < ntiles; it++) {
        const int ks = it << 6;
        if (it + 1 < ntiles) { CP_WAIT(1); } else { CP_WAIT(0); }
        __syncthreads();
        if (it + 2 < ntiles) {
            stage_kv_async(sb + (uint32_t)pslot * A_BSTRIDE, b, ks + 128, tid);
            CP_COMMIT();
        }
        const uint32_t kvb = sb + (uint32_t)cslot * A_BSTRIDE;
        cslot = (cslot == 2) ? 0 : cslot + 1;
        pslot = (pslot == 2) ? 0 : pslot + 1;

        // ---- S = Q K^T : qh*kh + qh*kl ----
        float sc[8][4];
#pragma unroll
        for (int nt = 0; nt < 8; nt++) {
            int row = (nt << 3) + brow;
            uint32_t rb = kvb + (uint32_t)row * 128u;
            uint32_t s0 = (uint32_t)((bu       ^ (row & 7)) << 4);
            uint32_t s1 = (uint32_t)(((4 + bu) ^ (row & 7)) << 4);
            uint32_t kh8[8], kl8[8];
            ldsm4(kh8,     rb + A_KHI + s0);
            ldsm4(kh8 + 4, rb + A_KHI + s1);
            ldsm4(kl8,     rb + A_KLO + s0);
            ldsm4(kl8 + 4, rb + A_KLO + s1);
#pragma unroll
            for (int j = 0; j < 4; j++) sc[nt][j] = 0.f;
#pragma unroll
            for (int s = 0; s < 4; s++) {
                mma16816h(sc[nt], qh[s], kh8[2 * s], kh8[2 * s + 1]);
                mma16816h(sc[nt], qh[s], kl8[2 * s], kl8[2 * s + 1]);
            }
        }

        // ---- causal mask (diagonal tile only) ----
        const int R0 = wrow0 + (l >> 2);
        if (ks + 64 > wrow0) {
            int colb = ks + ((l & 3) << 1);
#pragma unroll
            for (int nt = 0; nt < 8; nt++) {
                int c0 = colb + (nt << 3);
                if (c0     > R0)     sc[nt][0] = -3.0e38f;
                if (c0 + 1 > R0)     sc[nt][1] = -3.0e38f;
                if (c0     > R0 + 8) sc[nt][2] = -3.0e38f;
                if (c0 + 1 > R0 + 8) sc[nt][3] = -3.0e38f;
            }
        }

        // ---- online softmax (exp2 domain) ----
        float tm0 = -3.0e38f, tm1 = -3.0e38f;
#pragma unroll
        for (int nt = 0; nt < 8; nt++) {
            tm0 = fmaxf(tm0, fmaxf(sc[nt][0], sc[nt][1]));
            tm1 = fmaxf(tm1, fmaxf(sc[nt][2], sc[nt][3]));
        }
        tm0 = fmaxf(tm0, __shfl_xor_sync(0xffffffffu, tm0, 1));
        tm0 = fmaxf(tm0, __shfl_xor_sync(0xffffffffu, tm0, 2));
        tm1 = fmaxf(tm1, __shfl_xor_sync(0xffffffffu, tm1, 1));
        tm1 = fmaxf(tm1, __shfl_xor_sync(0xffffffffu, tm1, 2));
        float mn0 = fmaxf(m0, tm0), mn1 = fmaxf(m1, tm1);
        float c0 = ex2f(m0 - mn0), c1 = ex2f(m1 - mn1);

        float ps0 = 0.f, ps1 = 0.f;
        uint32_t phi[4][4];
#pragma unroll
        for (int s = 0; s < 4; s++) {
#pragma unroll
            for (int h = 0; h < 2; h++) {
                int nt = 2 * s + h;
                float p0 = ex2f(sc[nt][0] - mn0);
                float p1 = ex2f(sc[nt][1] - mn0);
                float p2 = ex2f(sc[nt][2] - mn1);
                float p3 = ex2f(sc[nt][3] - mn1);
                ps0 += p0 + p1;
                ps1 += p2 + p3;
                phi[s][2 * h]     = packh2(p0, p1);
                phi[s][2 * h + 1] = packh2(p2, p3);
            }
        }
        ps0 += __shfl_xor_sync(0xffffffffu, ps0, 1);
        ps0 += __shfl_xor_sync(0xffffffffu, ps0, 2);
        ps1 += __shfl_xor_sync(0xffffffffu, ps1, 1);
        ps1 += __shfl_xor_sync(0xffffffffu, ps1, 2);
        ls0 = ls0 * c0 + ps0;
        ls1 = ls1 * c1 + ps1;
        m0 = mn0; m1 = mn1;

        // ---- O = O*c + P V : ph*vh (V single-term) ----
#pragma unroll
        for (int nt = 0; nt < 8; nt++) {
            o[nt][0] *= c0; o[nt][1] *= c0;
            o[nt][2] *= c1; o[nt][3] *= c1;
        }
#pragma unroll
        for (int nt = 0; nt < 8; nt++) {
            int row = (nt << 3) + brow;
            uint32_t rb = kvb + (uint32_t)row * 128u;
            uint32_t s0 = (uint32_t)((bu       ^ (row & 7)) << 4);
            uint32_t s1 = (uint32_t)(((4 + bu) ^ (row & 7)) << 4);
            uint32_t vh8[8];
            ldsm4(vh8,     rb + A_VHI + s0);
            ldsm4(vh8 + 4, rb + A_VHI + s1);
#pragma unroll
            for (int s = 0; s < 4; s++) {
                mma16816h(o[nt], phi[s], vh8[2 * s], vh8[2 * s + 1]);
            }
        }
    }

    const float inv0 = 1.f / ls0, inv1 = 1.f / ls1;
    const int R0g = q0 + (w << 4) + (l >> 2);
    float* o0p = out + (((size_t)(b * Tn + R0g)) << 6) + ((l & 3) << 1);
    float* o1p = o0p + (8 << 6);
#pragma unroll
    for (int nt = 0; nt < 8; nt++) {
        *(float2*)(o0p + (nt << 3)) = make_float2(o[nt][0] * inv0, o[nt][1] * inv0);
        *(float2*)(o1p + (nt << 3)) = make_float2(o[nt][2] * inv1, o[nt][3] * inv1);
    }
}

// ===================== launch =====================
extern "C" void kernel_launch(void* const* d_in, const int* in_sizes, int n_in,
                              void* d_out, int out_size)
{
    const float* x  = (const float*)d_in[0];
    const float* WQ = (const float*)d_in[1];
    const float* WK = (const float*)d_in[2];
    const float* WV = (const float*)d_in[3];
    float* out = (float*)d_out;

    cudaFuncSetAttribute(proj_tc_kernel,
                         cudaFuncAttributeMaxDynamicSharedMemorySize, PROJ_SMEM);
    cudaFuncSetAttribute(attn_kernel,
                         cudaFuncAttributeMaxDynamicSharedMemorySize, ATTN_SMEM);

    prep_w<<<18, 256>>>(WQ, WK, WV);
    proj_tc_kernel<<<256, 256, PROJ_SMEM>>>(x);
    attn_kernel<<<512, 128, ATTN_SMEM>>>(out);
}